// round 10
// baseline (speedup 1.0000x reference)
#include <cuda_runtime.h>
#include <cuda_fp16.h>

#define NN 4096

// fp16 complex scratch for the stage-8 intermediate (67 MB).
__device__ __half2 g_scr[(size_t)NN * NN];

// butterfly: (top, bot) -> (top + tw*bot, top - tw*bot), tw = cs + i*sn
static __device__ __forceinline__ void bf(float& tr_, float& ti_,
                                          float& br_, float& bi_,
                                          float cs, float sn) {
    float tr = cs * br_ - sn * bi_;
    float ti = cs * bi_ + sn * br_;
    br_ = tr_ - tr;
    bi_ = ti_ - ti;
    tr_ += tr;
    ti_ += ti;
}

// phase = (-2*pi) * (k/4096) * W[k,d], fp32, reference rounding order
static __device__ __forceinline__ float phase_of(int k, float w) {
    return (-6.2831855f) * ((float)k * (1.0f / 4096.0f)) * w;
}

// ---------------------------------------------------------------------------
// Kernel A (R8 base + round-1 twiddle dedup): permutation + stages 2..256.
// CTA = 256-row group x 16-column tile, 256 threads (m = tx>>4, c = tx&15).
// Round-1 twiddles (stages 2..16) are m-invariant: 15 unique (s,r) per column.
// 240 threads compute them once into smtw; all threads then read (16x fewer
// sincos). Round 2 (stages 32..256) twiddles depend on m -> computed inline.
// ---------------------------------------------------------------------------
__global__ __launch_bounds__(256) void fftA(const float* __restrict__ x,
                                            const float* __restrict__ W) {
    __shared__ float2 sm[256 * 16];   // 32 KB exchange
    __shared__ float2 smtw[15 * 16];  // round-1 twiddles [idx][c]
    const int tx = threadIdx.x;
    const int m  = tx >> 4;           // 0..15
    const int c  = tx & 15;           // 0..15
    const int d  = blockIdx.x * 16 + c;
    const int g  = blockIdx.y;        // 0..15
    const int gin = g ^ 8;            // i^2048 flips group bit 3

    // Cooperative round-1 twiddle computation: idx 0..14 enumerates (s,r)
    // as idx = (1<<(s-1))-1 + r  (s=1..4, r=0..2^(s-1)-1).
    if (tx < 240) {
        const int idx = tx >> 4;          // 0..14
        const int cc  = tx & 15;
        const int n1  = idx + 1;          // 1..15
        const int s   = 31 - __clz(n1) + 1;   // 1..4
        const int r   = n1 - (1 << (s - 1));
        const int k   = r << (12 - s);
        const int dd  = blockIdx.x * 16 + cc;
        float sn, cs;
        __sincosf(phase_of(k, W[(size_t)k * NN + dd]), &sn, &cs);
        smtw[idx * 16 + cc] = make_float2(cs, sn);
    }

    float re[16], im[16];

    // Load 16 contiguous rows of column d from the permuted source group.
    {
        const float* xp = x + (size_t)(gin * 256 + m * 16) * NN + d;
        #pragma unroll
        for (int i = 0; i < 16; ++i) {
            re[i] = xp[(size_t)i * NN];
            im[i] = 0.0f;
        }
    }

    __syncthreads();   // twiddles ready

    // Stages step = 2,4,8,16 : twiddles from SMEM (constant offsets).
    #pragma unroll
    for (int s = 1; s <= 4; ++s) {
        const int step = 1 << s, half = step >> 1;
        #pragma unroll
        for (int r = 0; r < half; ++r) {
            const float2 tw = smtw[((1 << (s - 1)) - 1 + r) * 16 + c];
            const float cs = tw.x, sn = tw.y;
            #pragma unroll
            for (int bb = 0; bb < 16; bb += step) {
                const int j = bb + r;
                bf(re[j], im[j], re[j + half], im[j + half], cs, sn);
            }
        }
    }

    __syncthreads();   // smtw reads done before sm reuse? (separate arrays, but
                       // keep exchange ordering below intact)

    // Exchange: write rows m*16+i, read rows m+16j.
    #pragma unroll
    for (int i = 0; i < 16; ++i)
        sm[(m * 16 + i) * 16 + c] = make_float2(re[i], im[i]);
    __syncthreads();
    #pragma unroll
    for (int j = 0; j < 16; ++j) {
        float2 v = sm[(m + 16 * j) * 16 + c];
        re[j] = v.x;
        im[j] = v.y;
    }

    // Stages step = 32,64,128,256 : local row l = m + 16j (k depends on m).
    #pragma unroll
    for (int s = 5; s <= 8; ++s) {
        const int jstep = 1 << (s - 4), jhalf = jstep >> 1;
        #pragma unroll
        for (int rr = 0; rr < jhalf; ++rr) {
            const int k = (m + 16 * rr) << (12 - s);
            float sn, cs;
            __sincosf(phase_of(k, W[(size_t)k * NN + d]), &sn, &cs);
            #pragma unroll
            for (int jb = 0; jb < 16; jb += jstep) {
                const int j = jb + rr;
                bf(re[j], im[j], re[j + jhalf], im[j + jhalf], cs, sn);
            }
        }
    }

    // Store rows g*256 + m + 16j as packed half2.
    {
        __half2* sp = g_scr + (size_t)(g * 256 + m) * NN + d;
        #pragma unroll
        for (int j = 0; j < 16; ++j)
            sp[(size_t)(16 * j) * NN] = __floats2half2_rn(re[j], im[j]);
    }
}

// ---------------------------------------------------------------------------
// Kernel B (unchanged — at its memory floor): stages step = 512..4096.
// ---------------------------------------------------------------------------
__global__ __launch_bounds__(256) void fftB(const float* __restrict__ W,
                                            float* __restrict__ out) {
    const int d = blockIdx.x * 256 + threadIdx.x;  // grid.x = 16
    const int b = blockIdx.y;                      // 0..255

    float re[16], im[16];
    {
        const __half2* sp = g_scr + (size_t)b * NN + d;
        #pragma unroll
        for (int a = 0; a < 16; ++a) {
            float2 v = __half22float2(sp[(size_t)(a * 256) * NN]);
            re[a] = v.x;
            im[a] = v.y;
        }
    }

    #pragma unroll
    for (int s = 9; s <= 12; ++s) {
        const int astep = 1 << (s - 8), ahalf = astep >> 1;
        #pragma unroll
        for (int rr = 0; rr < ahalf; ++rr) {
            const int k = (256 * rr + b) << (12 - s);
            float sn, cs;
            __sincosf(phase_of(k, W[(size_t)k * NN + d]), &sn, &cs);
            #pragma unroll
            for (int ab = 0; ab < 16; ab += astep) {
                const int a = ab + rr;
                bf(re[a], im[a], re[a + ahalf], im[a + ahalf], cs, sn);
            }
        }
    }

    {
        float* op = out + (size_t)b * NN + d;
        #pragma unroll
        for (int a = 0; a < 16; ++a)
            op[(size_t)(a * 256) * NN] = re[a];
    }
}

extern "C" void kernel_launch(void* const* d_in, const int* in_sizes, int n_in,
                              void* d_out, int out_size) {
    if (n_in < 2 || d_in == nullptr || d_out == nullptr || in_sizes == nullptr)
        return;
    if (d_in[0] == nullptr || d_in[1] == nullptr)
        return;
    if (in_sizes[0] < NN * NN || in_sizes[1] < NN * NN)
        return;
    if (out_size < NN * NN)
        return;

    const float* x = (const float*)d_in[0]; // (4096,4096) float32
    const float* W = (const float*)d_in[1]; // (4096,4096) float32 weights
    float* out = (float*)d_out;             // (4096,4096) float32 = Re(FFT)

    dim3 gA(NN / 16, 16);   // 256 column tiles x 16 row groups, 256 thr
    fftA<<<gA, 256>>>(x, W);

    dim3 gB(NN / 256, 256); // 16 column tiles x 256 b-values
    fftB<<<gB, 256>>>(W, out);
}

// round 11
// speedup vs baseline: 1.0220x; 1.0220x over previous
#include <cuda_runtime.h>
#include <cuda_fp16.h>

#define NN 4096

// fp16 complex scratch for the stage-8 intermediate (67 MB).
__device__ __half2 g_scr[(size_t)NN * NN];

// butterfly: (top, bot) -> (top + tw*bot, top - tw*bot), tw = cs + i*sn
static __device__ __forceinline__ void bf(float& tr_, float& ti_,
                                          float& br_, float& bi_,
                                          float cs, float sn) {
    float tr = cs * br_ - sn * bi_;
    float ti = cs * bi_ + sn * br_;
    br_ = tr_ - tr;
    bi_ = ti_ - ti;
    tr_ += tr;
    ti_ += ti;
}

// phase = (-2*pi) * (k/4096) * W[k,d], fp32, reference rounding order
static __device__ __forceinline__ float phase_of(int k, float w) {
    return (-6.2831855f) * ((float)k * (1.0f / 4096.0f)) * w;
}

// ---------------------------------------------------------------------------
// Kernel A (R8 base + full W prefetch): permutation + stages step=2..256.
// CTA = 256-row group x 16-column tile, 256 threads (m = tx>>4, c = tx&15).
// All 16 x-loads and all 30 W-loads are issued up front (MLP ~46/thread),
// removing the per-stage W-load latency from the butterfly dependency chain.
// ---------------------------------------------------------------------------
__global__ __launch_bounds__(256) void fftA(const float* __restrict__ x,
                                            const float* __restrict__ W) {
    __shared__ float2 sm[256 * 16];   // 32 KB exchange
    const int tx = threadIdx.x;
    const int m  = tx >> 4;           // 0..15
    const int c  = tx & 15;           // 0..15
    const int d  = blockIdx.x * 16 + c;
    const int g  = blockIdx.y;        // 0..15
    const int gin = g ^ 8;            // i^2048 flips group bit 3

    float re[16], im[16];

    // --- Front-batched loads: x (DRAM) first, then all W (L2-heavy). ---
    {
        const float* xp = x + (size_t)(gin * 256 + m * 16) * NN + d;
        #pragma unroll
        for (int i = 0; i < 16; ++i) {
            re[i] = xp[(size_t)i * NN];
            im[i] = 0.0f;
        }
    }

    // Round-1 W values: idx = (1<<(s-1))-1 + r for s=1..4, k = r<<(12-s).
    float w1[15];
    #pragma unroll
    for (int s = 1; s <= 4; ++s) {
        const int base = (1 << (s - 1)) - 1;
        #pragma unroll
        for (int r = 0; r < (1 << (s - 1)); ++r) {
            const int k = r << (12 - s);
            w1[base + r] = W[(size_t)k * NN + d];
        }
    }
    // Round-2 W values: idx = (1<<(s-5))-1 + rr for s=5..8, k = (m+16rr)<<(12-s).
    float w2[15];
    #pragma unroll
    for (int s = 5; s <= 8; ++s) {
        const int base = (1 << (s - 5)) - 1;
        #pragma unroll
        for (int rr = 0; rr < (1 << (s - 5)); ++rr) {
            const int k = (m + 16 * rr) << (12 - s);
            w2[base + rr] = W[(size_t)k * NN + d];
        }
    }

    // --- Round 1: stages step = 2,4,8,16 (local row l = m*16+i). ---
    #pragma unroll
    for (int s = 1; s <= 4; ++s) {
        const int step = 1 << s, half = step >> 1;
        const int base = half - 1;
        #pragma unroll
        for (int r = 0; r < half; ++r) {
            const int k = r << (12 - s);
            float sn, cs;
            __sincosf(phase_of(k, w1[base + r]), &sn, &cs);
            #pragma unroll
            for (int bb = 0; bb < 16; bb += step) {
                const int j = bb + r;
                bf(re[j], im[j], re[j + half], im[j + half], cs, sn);
            }
        }
    }

    // --- Exchange: write rows m*16+i, read rows m+16j. ---
    #pragma unroll
    for (int i = 0; i < 16; ++i)
        sm[(m * 16 + i) * 16 + c] = make_float2(re[i], im[i]);
    __syncthreads();
    #pragma unroll
    for (int j = 0; j < 16; ++j) {
        float2 v = sm[(m + 16 * j) * 16 + c];
        re[j] = v.x;
        im[j] = v.y;
    }

    // --- Round 2: stages step = 32,64,128,256 (local row l = m + 16j). ---
    #pragma unroll
    for (int s = 5; s <= 8; ++s) {
        const int jstep = 1 << (s - 4), jhalf = jstep >> 1;
        const int base = jhalf - 1;
        #pragma unroll
        for (int rr = 0; rr < jhalf; ++rr) {
            const int k = (m + 16 * rr) << (12 - s);
            float sn, cs;
            __sincosf(phase_of(k, w2[base + rr]), &sn, &cs);
            #pragma unroll
            for (int jb = 0; jb < 16; jb += jstep) {
                const int j = jb + rr;
                bf(re[j], im[j], re[j + jhalf], im[j + jhalf], cs, sn);
            }
        }
    }

    // --- Store rows g*256 + m + 16j as packed half2. ---
    {
        __half2* sp = g_scr + (size_t)(g * 256 + m) * NN + d;
        #pragma unroll
        for (int j = 0; j < 16; ++j)
            sp[(size_t)(16 * j) * NN] = __floats2half2_rn(re[j], im[j]);
    }
}

// ---------------------------------------------------------------------------
// Kernel B (unchanged — at its memory floor): stages step = 512..4096.
// ---------------------------------------------------------------------------
__global__ __launch_bounds__(256) void fftB(const float* __restrict__ W,
                                            float* __restrict__ out) {
    const int d = blockIdx.x * 256 + threadIdx.x;  // grid.x = 16
    const int b = blockIdx.y;                      // 0..255

    float re[16], im[16];
    {
        const __half2* sp = g_scr + (size_t)b * NN + d;
        #pragma unroll
        for (int a = 0; a < 16; ++a) {
            float2 v = __half22float2(sp[(size_t)(a * 256) * NN]);
            re[a] = v.x;
            im[a] = v.y;
        }
    }

    #pragma unroll
    for (int s = 9; s <= 12; ++s) {
        const int astep = 1 << (s - 8), ahalf = astep >> 1;
        #pragma unroll
        for (int rr = 0; rr < ahalf; ++rr) {
            const int k = (256 * rr + b) << (12 - s);
            float sn, cs;
            __sincosf(phase_of(k, W[(size_t)k * NN + d]), &sn, &cs);
            #pragma unroll
            for (int ab = 0; ab < 16; ab += astep) {
                const int a = ab + rr;
                bf(re[a], im[a], re[a + ahalf], im[a + ahalf], cs, sn);
            }
        }
    }

    {
        float* op = out + (size_t)b * NN + d;
        #pragma unroll
        for (int a = 0; a < 16; ++a)
            op[(size_t)(a * 256) * NN] = re[a];
    }
}

extern "C" void kernel_launch(void* const* d_in, const int* in_sizes, int n_in,
                              void* d_out, int out_size) {
    if (n_in < 2 || d_in == nullptr || d_out == nullptr || in_sizes == nullptr)
        return;
    if (d_in[0] == nullptr || d_in[1] == nullptr)
        return;
    if (in_sizes[0] < NN * NN || in_sizes[1] < NN * NN)
        return;
    if (out_size < NN * NN)
        return;

    const float* x = (const float*)d_in[0]; // (4096,4096) float32
    const float* W = (const float*)d_in[1]; // (4096,4096) float32 weights
    float* out = (float*)d_out;             // (4096,4096) float32 = Re(FFT)

    dim3 gA(NN / 16, 16);   // 256 column tiles x 16 row groups, 256 thr
    fftA<<<gA, 256>>>(x, W);

    dim3 gB(NN / 256, 256); // 16 column tiles x 256 b-values
    fftB<<<gB, 256>>>(W, out);
}

// round 12
// speedup vs baseline: 1.0577x; 1.0349x over previous
#include <cuda_runtime.h>
#include <cuda_fp16.h>

#define NN 4096

// fp16 complex scratch for the stage-8 intermediate (67 MB).
__device__ __half2 g_scr[(size_t)NN * NN];

static __device__ __forceinline__ void bf(float& tr_, float& ti_,
                                          float& br_, float& bi_,
                                          float cs, float sn) {
    float tr = cs * br_ - sn * bi_;
    float ti = cs * bi_ + sn * br_;
    br_ = tr_ - tr;
    bi_ = ti_ - ti;
    tr_ += tr;
    ti_ += ti;
}

// phase = (-2*pi) * (k/4096) * W[k,d], fp32, reference rounding order
static __device__ __forceinline__ float phase_of(int k, float w) {
    return (-6.2831855f) * ((float)k * (1.0f / 4096.0f)) * w;
}

// ---------------------------------------------------------------------------
// Kernel A (2 columns/thread): permutation + stages step=2..256.
// CTA = 256-row group x 16-column tile, 128 threads: m = tx>>3 (16 row slots),
// cp = tx&7 (8 column pairs) -> thread owns columns d0 = 2*cp, d0+1.
// All global accesses are 8B/thread (float2 / uint2).
// ---------------------------------------------------------------------------
__global__ __launch_bounds__(128) void fftA(const float* __restrict__ x,
                                            const float* __restrict__ W) {
    __shared__ float4 sm[256 * 8];    // 32 KB exchange: [row][cp] = re0,im0,re1,im1
    const int tx = threadIdx.x;
    const int m  = tx >> 3;           // 0..15
    const int cp = tx & 7;            // 0..7
    const int d0 = blockIdx.x * 16 + 2 * cp;
    const int g  = blockIdx.y;        // 0..15
    const int gin = g ^ 8;            // i^2048 flips group bit 3

    float re0[16], im0[16], re1[16], im1[16];

    // Load 16 rows x 2 cols (float2, 8B aligned since d0 is even).
    {
        const float* xp = x + (size_t)(gin * 256 + m * 16) * NN + d0;
        #pragma unroll
        for (int i = 0; i < 16; ++i) {
            float2 v = *reinterpret_cast<const float2*>(xp + (size_t)i * NN);
            re0[i] = v.x; im0[i] = 0.0f;
            re1[i] = v.y; im1[i] = 0.0f;
        }
    }

    // Stages step = 2,4,8,16 : local row l = m*16+i, r = i mod step.
    #pragma unroll
    for (int s = 1; s <= 4; ++s) {
        const int step = 1 << s, half = step >> 1;
        #pragma unroll
        for (int r = 0; r < half; ++r) {
            const int k = r << (12 - s);
            const float2 w = *reinterpret_cast<const float2*>(W + (size_t)k * NN + d0);
            float sn0, cs0, sn1, cs1;
            __sincosf(phase_of(k, w.x), &sn0, &cs0);
            __sincosf(phase_of(k, w.y), &sn1, &cs1);
            #pragma unroll
            for (int bb = 0; bb < 16; bb += step) {
                const int j = bb + r;
                bf(re0[j], im0[j], re0[j + half], im0[j + half], cs0, sn0);
                bf(re1[j], im1[j], re1[j + half], im1[j + half], cs1, sn1);
            }
        }
    }

    // Exchange: write rows m*16+i, read rows m+16j. float4 accesses; warp
    // covers 8 consecutive cp per row-slot -> 128B contiguous, conflict-free.
    #pragma unroll
    for (int i = 0; i < 16; ++i)
        sm[(m * 16 + i) * 8 + cp] = make_float4(re0[i], im0[i], re1[i], im1[i]);
    __syncthreads();
    #pragma unroll
    for (int j = 0; j < 16; ++j) {
        float4 v = sm[(m + 16 * j) * 8 + cp];
        re0[j] = v.x; im0[j] = v.y;
        re1[j] = v.z; im1[j] = v.w;
    }

    // Stages step = 32,64,128,256 : local row l = m + 16j.
    #pragma unroll
    for (int s = 5; s <= 8; ++s) {
        const int jstep = 1 << (s - 4), jhalf = jstep >> 1;
        #pragma unroll
        for (int rr = 0; rr < jhalf; ++rr) {
            const int k = (m + 16 * rr) << (12 - s);
            const float2 w = *reinterpret_cast<const float2*>(W + (size_t)k * NN + d0);
            float sn0, cs0, sn1, cs1;
            __sincosf(phase_of(k, w.x), &sn0, &cs0);
            __sincosf(phase_of(k, w.y), &sn1, &cs1);
            #pragma unroll
            for (int jb = 0; jb < 16; jb += jstep) {
                const int j = jb + rr;
                bf(re0[j], im0[j], re0[j + jhalf], im0[j + jhalf], cs0, sn0);
                bf(re1[j], im1[j], re1[j + jhalf], im1[j + jhalf], cs1, sn1);
            }
        }
    }

    // Store rows g*256 + m + 16j: two half2 packed into one uint2 (8B).
    {
        const size_t base = (size_t)(g * 256 + m) * NN + d0;
        #pragma unroll
        for (int j = 0; j < 16; ++j) {
            const size_t idx = base + (size_t)(16 * j) * NN;
            union { __half2 h[2]; uint2 u; } pk;
            pk.h[0] = __floats2half2_rn(re0[j], im0[j]);
            pk.h[1] = __floats2half2_rn(re1[j], im1[j]);
            *reinterpret_cast<uint2*>(g_scr + idx) = pk.u;
        }
    }
}

// ---------------------------------------------------------------------------
// Kernel B (2 columns/thread): stages step = 512..4096. Row i = a*256 + b.
// 256 threads cover 512 columns per CTA: d0 = blockIdx.x*512 + 2*tx.
// Scratch loads uint2 (8B), W loads float2, out stores float2.
// ---------------------------------------------------------------------------
__global__ __launch_bounds__(256) void fftB(const float* __restrict__ W,
                                            float* __restrict__ out) {
    const int d0 = blockIdx.x * 512 + 2 * threadIdx.x; // grid.x = 8
    const int b  = blockIdx.y;                         // 0..255

    float re0[16], im0[16], re1[16], im1[16];
    {
        const size_t base = (size_t)b * NN + d0;
        #pragma unroll
        for (int a = 0; a < 16; ++a) {
            const size_t idx = base + (size_t)(a * 256) * NN;
            union { uint2 u; __half2 h[2]; } pk;
            pk.u = *reinterpret_cast<const uint2*>(g_scr + idx);
            float2 v0 = __half22float2(pk.h[0]);
            float2 v1 = __half22float2(pk.h[1]);
            re0[a] = v0.x; im0[a] = v0.y;
            re1[a] = v1.x; im1[a] = v1.y;
        }
    }

    #pragma unroll
    for (int s = 9; s <= 12; ++s) {
        const int astep = 1 << (s - 8), ahalf = astep >> 1;
        #pragma unroll
        for (int rr = 0; rr < ahalf; ++rr) {
            const int k = (256 * rr + b) << (12 - s);
            const float2 w = *reinterpret_cast<const float2*>(W + (size_t)k * NN + d0);
            float sn0, cs0, sn1, cs1;
            __sincosf(phase_of(k, w.x), &sn0, &cs0);
            __sincosf(phase_of(k, w.y), &sn1, &cs1);
            #pragma unroll
            for (int ab = 0; ab < 16; ab += astep) {
                const int a = ab + rr;
                bf(re0[a], im0[a], re0[a + ahalf], im0[a + ahalf], cs0, sn0);
                bf(re1[a], im1[a], re1[a + ahalf], im1[a + ahalf], cs1, sn1);
            }
        }
    }

    // Emit real parts: float2 per row (8B).
    {
        const size_t base = (size_t)b * NN + d0;
        #pragma unroll
        for (int a = 0; a < 16; ++a)
            *reinterpret_cast<float2*>(out + base + (size_t)(a * 256) * NN) =
                make_float2(re0[a], re1[a]);
    }
}

extern "C" void kernel_launch(void* const* d_in, const int* in_sizes, int n_in,
                              void* d_out, int out_size) {
    if (n_in < 2 || d_in == nullptr || d_out == nullptr || in_sizes == nullptr)
        return;
    if (d_in[0] == nullptr || d_in[1] == nullptr)
        return;
    if (in_sizes[0] < NN * NN || in_sizes[1] < NN * NN)
        return;
    if (out_size < NN * NN)
        return;

    const float* x = (const float*)d_in[0]; // (4096,4096) float32
    const float* W = (const float*)d_in[1]; // (4096,4096) float32 weights
    float* out = (float*)d_out;             // (4096,4096) float32 = Re(FFT)

    dim3 gA(NN / 16, 16);   // 256 column tiles x 16 row groups, 128 thr
    fftA<<<gA, 128>>>(x, W);

    dim3 gB(NN / 512, 256); // 8 column tiles x 256 b-values, 256 thr
    fftB<<<gB, 256>>>(W, out);
}